// round 4
// baseline (speedup 1.0000x reference)
#include <cuda_runtime.h>
#include <cstdint>
#include <cstring>

#define BATCH 256
#define TT    2048
#define YW    288   // [0:128)=Ys (y@BK2), [128:256)=Yv (y@DK3), [256:288)=Yu (y@DK2)

typedef unsigned long long u64;

// 604 MB scratch for the time-parallel precompute
__device__ float g_Y[(size_t)BATCH * TT * YW];

// ---------------------------------------------------------------------------
// helpers
// ---------------------------------------------------------------------------
__device__ __forceinline__ void cp16(void* s, const void* g) {
    unsigned saddr = (unsigned)__cvta_generic_to_shared(s);
    asm volatile("cp.async.cg.shared.global [%0], [%1], 16;\n" :: "r"(saddr), "l"(g));
}
__device__ __forceinline__ void cp_commit() { asm volatile("cp.async.commit_group;\n"); }
__device__ __forceinline__ void cp_wait0()  { asm volatile("cp.async.wait_group 0;\n"); }

// packed f32x2 FMA: d = a*b + d  (Blackwell)
__device__ __forceinline__ void ffma2(u64& d, u64 a, u64 b) {
    asm("fma.rn.f32x2 %0, %1, %2, %0;" : "+l"(d) : "l"(a), "l"(b));
}
__device__ __forceinline__ u64 packf2(float lo, float hi) {
    float2 t; t.x = lo; t.y = hi; u64 r; memcpy(&r, &t, 8); return r;
}
__device__ __forceinline__ float sum2(u64 v) {
    float2 t; memcpy(&t, &v, 8); return t.x + t.y;
}

// Accurate tanh independent of --use_fast_math: (e^{2v}-1)/(e^{2v}+1) via EX2
__device__ __forceinline__ float tanh_acc(float x) {
    float xc = fminf(fmaxf(x, -15.f), 15.f);
    float e  = exp2f(xc * 2.8853900817779268f);   // 2*log2(e)
    return (e - 1.f) / (e + 1.f);
}

// ---------------------------------------------------------------------------
// Kernel 1: Y[m][0:288] = obs[m][:] @ [BK2 | DK3 | DK2]^T
// Column-split across CTA pairs: 296 CTAs (2/SM), each holds 144 columns.
// 288 threads: thread = (col_local 0..143, row-half 0/1); 16 rows x 1 col.
// ---------------------------------------------------------------------------
__global__ __launch_bounds__(288, 2)
void precompute_y_kernel(const float* __restrict__ obs,
                         const float* __restrict__ BK2,
                         const float* __restrict__ DK3,
                         const float* __restrict__ DK2)
{
    extern __shared__ float sm[];
    float* W1T = sm;                  // [144][132]
    float* ob0 = sm + 144 * 132;      // [32][128]
    float* ob1 = ob0 + 4096;

    const int tid  = threadIdx.x;
    const int half = blockIdx.x & 1;          // which 144-column half
    const int cbase = half * 144;

    // Load this half's W1 transposed (one-time)
    for (int idx = tid; idx < 144 * 128; idx += 288) {
        int nl = idx >> 7, k = idx & 127;
        int n = cbase + nl;
        float v;
        if      (n < 128) v = BK2[k * 128 + n];
        else if (n < 256) v = DK3[k * 128 + (n - 128)];
        else              v = DK2[k * 32  + (n - 256)];
        W1T[nl * 132 + k] = v;
    }

    const int NCH = (BATCH * TT) / 32;        // 16384 chunks of 32 rows
    const int stride = gridDim.x >> 1;        // 148
    int chunk = blockIdx.x >> 1;

    {   // prologue
        const float* src = obs + (size_t)chunk * 32 * 128;
        for (int i = tid; i < 1024; i += 288)
            cp16(&ob0[i * 4], &src[i * 4]);
        cp_commit(); cp_wait0();
    }
    __syncthreads();

    const int nl    = tid % 144;
    const int rbase = (tid / 144) * 16;       // 0 or 16
    const ulonglong2* w2 = (const ulonglong2*)(W1T + nl * 132);
    const int ncol = cbase + nl;

    int p = 0;
    for (; chunk < NCH; chunk += stride) {
        float* cur = p ? ob1 : ob0;
        float* nb  = p ? ob0 : ob1;
        int nxt = chunk + stride;
        if (nxt < NCH) {
            const float* src = obs + (size_t)nxt * 32 * 128;
            for (int i = tid; i < 1024; i += 288)
                cp16(&nb[i * 4], &src[i * 4]);
        }
        cp_commit();

        u64 acc[16];
        #pragma unroll
        for (int m = 0; m < 16; m++) acc[m] = 0ull;

        const float* crow = cur + rbase * 128;
        #pragma unroll 4
        for (int j = 0; j < 32; j++) {            // 4 k per iter
            ulonglong2 wv = w2[j];
            #pragma unroll
            for (int m = 0; m < 16; m++) {
                ulonglong2 o = *(const ulonglong2*)&crow[m * 128 + 4 * j];
                ffma2(acc[m], o.x, wv.x);
                ffma2(acc[m], o.y, wv.y);
            }
        }
        size_t base = (size_t)chunk * 32 * YW + (size_t)rbase * YW + ncol;
        #pragma unroll 4
        for (int m = 0; m < 16; m++)
            g_Y[base + (size_t)m * YW] = sum2(acc[m]);

        cp_wait0();
        __syncthreads();
        p ^= 1;
    }
}

// ---------------------------------------------------------------------------
// Kernel 2: sequential recurrence. 128 CTAs x 2 batch rows, 576 threads.
// k-split x2: each output column owned by a lane PAIR (kh = lane&1),
// combined via shfl.xor(1).
//   tid   0..255 (A):  col h, CK2 half-column in regs (32 x b64)
//   tid 256..575 (BC): col c (0..159); z-phase [BK1|DK1] half-col in regs;
//                      state-phase [AK|CK1] from smem (stride 136, kh off 68)
// ---------------------------------------------------------------------------
__global__ __launch_bounds__(576, 1)
void rnn_seq_kernel(const float* __restrict__ state0,
                    const float* __restrict__ AK,
                    const float* __restrict__ BK1,
                    const float* __restrict__ CK1,
                    const float* __restrict__ DK1,
                    const float* __restrict__ CK2,
                    const float* __restrict__ logstd,
                    float* __restrict__ out)
{
    extern __shared__ float sm[];
    float* W2sT = sm;                    // [160][136] state-phase weights
    float* st   = W2sT + 160 * 136;      // 2 bufs x (row0[128], row1[128])
    float* zz   = st + 512;              // row0[128], row1[128]

    const int tid  = threadIdx.x;
    const int lane = tid & 31;
    const int kh   = lane & 1;           // k-half
    const int b0 = blockIdx.x * 2, b1 = b0 + 1;

    const bool isA = (tid < 256);
    const int col = isA ? ((tid >> 5) * 16 + (lane >> 1))             // h: 0..127
                        : (((tid - 256) >> 5) * 16 + (lane >> 1));    // c: 0..159

    // smem: state-phase weights [AK | CK1], transposed, kh halves padded
    for (int idx = tid; idx < 160 * 128; idx += 576) {
        int c = idx >> 7, k = idx & 127;
        float v = (c < 128) ? AK[k * 128 + c] : CK1[k * 32 + (c - 128)];
        W2sT[c * 136 + (k >> 6) * 68 + (k & 63)] = v;
    }

    // register weights: 32 b64 covering k in [kh*64, kh*64+64)
    u64 wreg[32];
    {
        const int k0 = kh * 64;
        if (isA) {
            #pragma unroll
            for (int i = 0; i < 32; i++) {
                int k = k0 + 2 * i;
                wreg[i] = packf2(CK2[k * 128 + col], CK2[(k + 1) * 128 + col]);
            }
        } else {
            #pragma unroll
            for (int i = 0; i < 32; i++) {
                int k = k0 + 2 * i;
                float lo, hi;
                if (col < 128) { lo = BK1[k * 128 + col]; hi = BK1[(k + 1) * 128 + col]; }
                else { lo = DK1[k * 32 + (col - 128)]; hi = DK1[(k + 1) * 32 + (col - 128)]; }
                wreg[i] = packf2(lo, hi);
            }
        }
    }

    if (tid < 128) {
        st[tid]       = state0[b0 * 128 + tid];
        st[128 + tid] = state0[b1 * 128 + tid];
    }
    float ls = (!isA && col >= 128) ? logstd[col - 128] : 0.f;

    // Y column this thread consumes each step
    int yidx = isA ? (128 + col) : ((col < 128) ? col : (128 + col));
    const float* Y0 = g_Y + (size_t)b0 * TT * YW + yidx;
    const float* Y1 = g_Y + (size_t)b1 * TT * YW + yidx;

    __syncthreads();

    float y0 = __ldg(Y0), y1 = __ldg(Y1);
    float* cur = st;
    float* nxt = st + 256;

    const ulonglong2* wS = (const ulonglong2*)(W2sT + col * 136 + kh * 68);

    for (int t = 0; t < TT; t++) {
        int tn = (t + 1 < TT) ? (t + 1) : t;
        float ny0 = __ldg(Y0 + (size_t)tn * YW);
        float ny1 = __ldg(Y1 + (size_t)tn * YW);

        u64 a0a = 0, a0b = 0, a1a = 0, a1b = 0;
        const ulonglong2* s0 = (const ulonglong2*)(cur + kh * 64);
        const ulonglong2* s1 = (const ulonglong2*)(cur + 128 + kh * 64);

        if (isA) {
            // stage 1 (A): v = state @ CK2 + yv ; z = 2 tanh(v) - v
            #pragma unroll
            for (int i = 0; i < 16; i++) {
                ulonglong2 a = s0[i], b = s1[i];
                ffma2(a0a, a.x, wreg[2 * i]);
                ffma2(a0b, a.y, wreg[2 * i + 1]);
                ffma2(a1a, b.x, wreg[2 * i]);
                ffma2(a1b, b.y, wreg[2 * i + 1]);
            }
            float r0 = sum2(a0a) + sum2(a0b);
            float r1 = sum2(a1a) + sum2(a1b);
            r0 += __shfl_xor_sync(0xffffffffu, r0, 1);
            r1 += __shfl_xor_sync(0xffffffffu, r1, 1);
            if (kh == 0) {
                float v0 = y0 + r0, v1 = y1 + r1;
                zz[col]       = 2.f * tanh_acc(v0) - v0;
                zz[128 + col] = 2.f * tanh_acc(v1) - v1;
            }
        } else {
            // stage 1 (BC): acc = state @ [AK|CK1] (smem weights)
            #pragma unroll
            for (int i = 0; i < 16; i++) {
                ulonglong2 wv = wS[i];
                ulonglong2 a = s0[i], b = s1[i];
                ffma2(a0a, a.x, wv.x);
                ffma2(a0b, a.y, wv.y);
                ffma2(a1a, b.x, wv.x);
                ffma2(a1b, b.y, wv.y);
            }
        }
        __syncthreads();

        if (!isA) {
            // stage 2 (BC): acc += z @ [BK1|DK1] (reg weights)
            const ulonglong2* z0 = (const ulonglong2*)(zz + kh * 64);
            const ulonglong2* z1 = (const ulonglong2*)(zz + 128 + kh * 64);
            #pragma unroll
            for (int i = 0; i < 16; i++) {
                ulonglong2 a = z0[i], b = z1[i];
                ffma2(a0a, a.x, wreg[2 * i]);
                ffma2(a0b, a.y, wreg[2 * i + 1]);
                ffma2(a1a, b.x, wreg[2 * i]);
                ffma2(a1b, b.y, wreg[2 * i + 1]);
            }
            float r0 = sum2(a0a) + sum2(a0b);
            float r1 = sum2(a1a) + sum2(a1b);
            r0 += __shfl_xor_sync(0xffffffffu, r0, 1);
            r1 += __shfl_xor_sync(0xffffffffu, r1, 1);
            if (kh == 0) {
                r0 += y0; r1 += y1;
                if (col < 128) {
                    nxt[col]       = r0;
                    nxt[128 + col] = r1;
                } else {
                    int a = col - 128;
                    size_t o0 = ((size_t)b0 * TT + t) * 64;
                    size_t o1 = ((size_t)b1 * TT + t) * 64;
                    out[o0 + a] = r0; out[o0 + 32 + a] = ls;
                    out[o1 + a] = r1; out[o1 + 32 + a] = ls;
                }
            }
        }
        __syncthreads();

        float* tmp = cur; cur = nxt; nxt = tmp;
        y0 = ny0; y1 = ny1;
    }

    // state_final
    if (isA && kh == 0) {
        size_t base = (size_t)BATCH * TT * 64;
        out[base + b0 * 128 + col] = cur[col];
        out[base + b1 * 128 + col] = cur[128 + col];
    }
}

// ---------------------------------------------------------------------------
// kernel_launch
// Inputs: obs, state0, AK_tT, BK1_tT, BK2_tT, CK1_tT, DK1_tT, DK2_tT,
//         CK2_tT, DK3_tT, log_stds
// ---------------------------------------------------------------------------
extern "C" void kernel_launch(void* const* d_in, const int* in_sizes, int n_in,
                              void* d_out, int out_size)
{
    const float* obs    = (const float*)d_in[0];
    const float* state0 = (const float*)d_in[1];
    const float* AK     = (const float*)d_in[2];
    const float* BK1    = (const float*)d_in[3];
    const float* BK2    = (const float*)d_in[4];
    const float* CK1    = (const float*)d_in[5];
    const float* DK1    = (const float*)d_in[6];
    const float* DK2    = (const float*)d_in[7];
    const float* CK2    = (const float*)d_in[8];
    const float* DK3    = (const float*)d_in[9];
    const float* lstd   = (const float*)d_in[10];
    float* out = (float*)d_out;

    const int SMEM_PRE = (144 * 132 + 2 * 4096) * 4;            // 108800
    const int SMEM_RNN = (160 * 136 + 512 + 256) * 4;           // 90112

    cudaFuncSetAttribute(precompute_y_kernel,
                         cudaFuncAttributeMaxDynamicSharedMemorySize, SMEM_PRE);
    cudaFuncSetAttribute(rnn_seq_kernel,
                         cudaFuncAttributeMaxDynamicSharedMemorySize, SMEM_RNN);

    precompute_y_kernel<<<296, 288, SMEM_PRE>>>(obs, BK2, DK3, DK2);
    rnn_seq_kernel<<<BATCH / 2, 576, SMEM_RNN>>>(state0, AK, BK1, CK1, DK1,
                                                 CK2, lstd, out);
}